// round 1
// baseline (speedup 1.0000x reference)
#include <cuda_runtime.h>
#include <cstdint>

// dp[b,f,i,j] = relu(w0[f]*t[b,i] + w1[f]*t[b,j] + w2[f])
// t: (BSZ, SZ) fp32 ; w: (1, NF, 3, 1) fp32 ; out: (BSZ, NF, SZ*SZ) fp32
#define BSZ 16
#define SZ  512
#define NF  32

#define I_PER_BLOCK 64                 // i-rows per block
#define THREADS 512                    // 128 float4 columns x 4 row-lanes
#define IBLKS (SZ / I_PER_BLOCK)       // 8

__global__ __launch_bounds__(THREADS)
void pairwise_kernel(const float* __restrict__ t,
                     const float* __restrict__ w,
                     float* __restrict__ out) {
    // Decode (b, f, iblk) from blockIdx.x
    int bx   = blockIdx.x;
    int iblk = bx & (IBLKS - 1);
    int f    = (bx >> 3) & (NF - 1);
    int b    = bx >> 8;                // bx / (IBLKS*NF)

    const float w0 = __ldg(w + f * 3 + 0);
    const float w1 = __ldg(w + f * 3 + 1);
    const float w2 = __ldg(w + f * 3 + 2);

    const int tid = threadIdx.x;
    const int j4  = tid & 127;         // float4 column within a 512-wide row
    const int r   = tid >> 7;          // 0..3: row lane

    const float* trow = t + b * SZ;

    // Loop-invariant per-thread term: s_j = w1 * t[b, j] + w2  (4 j's)
    float4 tj = reinterpret_cast<const float4*>(trow)[j4];
    float4 s;
    s.x = fmaf(w1, tj.x, w2);
    s.y = fmaf(w1, tj.y, w2);
    s.z = fmaf(w1, tj.z, w2);
    s.w = fmaf(w1, tj.w, w2);

    const int i0 = iblk * I_PER_BLOCK;
    float4* outp = reinterpret_cast<float4*>(
        out + (((size_t)(b * NF + f) * SZ) + i0) * SZ);

    #pragma unroll 4
    for (int i = r; i < I_PER_BLOCK; i += 4) {
        float a = w0 * __ldg(trow + i0 + i);   // broadcast, L1-resident
        float4 o;
        o.x = fmaxf(a + s.x, 0.0f);
        o.y = fmaxf(a + s.y, 0.0f);
        o.z = fmaxf(a + s.z, 0.0f);
        o.w = fmaxf(a + s.w, 0.0f);
        outp[(size_t)i * (SZ / 4) + j4] = o;   // STG.128
    }
}

extern "C" void kernel_launch(void* const* d_in, const int* in_sizes, int n_in,
                              void* d_out, int out_size) {
    const float* t = (const float*)d_in[0];
    const float* w = (const float*)d_in[1];
    float* out = (float*)d_out;

    dim3 grid(BSZ * NF * IBLKS);   // 4096
    pairwise_kernel<<<grid, THREADS>>>(t, w, out);
}